// round 3
// baseline (speedup 1.0000x reference)
#include <cuda_runtime.h>
#include <cstdint>

#define NUM_USERS 200000
#define NUM_ITEMS 100000
#define NUM_NODES (NUM_USERS + NUM_ITEMS)
#define EMBED_DIM 64
#define NUM_EDGES 2000000

#define SCAN_CHUNK 1024
#define NUM_SCAN_BLOCKS ((NUM_NODES + SCAN_CHUNK - 1) / SCAN_CHUNK)  // 293

// ---- device-global scratch (no allocation allowed) ----
__device__ int       g_deg[NUM_NODES];
__device__ int       g_off[NUM_NODES + 1];
__device__ int       g_pos[NUM_NODES];
__device__ int       g_bsum[512];
__device__ int2      g_edge[NUM_EDGES];          // packed (src, weight-bits)
__device__ float     g_x1[(size_t)NUM_NODES * EMBED_DIM];

// ---- 1. histogram of dst degrees (int4-vectorized: 4 edges/thread) ----
__global__ void hist_kernel(const int* __restrict__ edge_dst) {
    int t = blockIdx.x * blockDim.x + threadIdx.x;
    int base = t * 4;
    if (base + 3 < NUM_EDGES) {
        int4 d = *(const int4*)(edge_dst + base);
        atomicAdd(&g_deg[d.x], 1);
        atomicAdd(&g_deg[d.y], 1);
        atomicAdd(&g_deg[d.z], 1);
        atomicAdd(&g_deg[d.w], 1);
    } else {
        for (int e = base; e < NUM_EDGES; e++)
            atomicAdd(&g_deg[__ldg(edge_dst + e)], 1);
    }
}

// ---- 2a. per-chunk sums ----
__global__ void block_sum_kernel() {
    __shared__ int s[SCAN_CHUNK];
    int t = threadIdx.x;
    int idx = blockIdx.x * SCAN_CHUNK + t;
    s[t] = (idx < NUM_NODES) ? g_deg[idx] : 0;
    __syncthreads();
    for (int o = SCAN_CHUNK / 2; o > 0; o >>= 1) {
        if (t < o) s[t] += s[t + o];
        __syncthreads();
    }
    if (t == 0) g_bsum[blockIdx.x] = s[0];
}

// ---- 2b. scan chunk sums (single block) ----
__global__ void scan_bsum_kernel() {
    __shared__ int s[512];
    int t = threadIdx.x;
    int v = (t < NUM_SCAN_BLOCKS) ? g_bsum[t] : 0;
    s[t] = v;
    __syncthreads();
    for (int o = 1; o < 512; o <<= 1) {
        int x = (t >= o) ? s[t - o] : 0;
        __syncthreads();
        s[t] += x;
        __syncthreads();
    }
    if (t < NUM_SCAN_BLOCKS) g_bsum[t] = s[t] - v;  // exclusive
}

// ---- 2c. per-chunk exclusive scan + chunk base -> offsets & cursors ----
__global__ void offsets_kernel() {
    __shared__ int s[SCAN_CHUNK];
    int t = threadIdx.x;
    int idx = blockIdx.x * SCAN_CHUNK + t;
    int v = (idx < NUM_NODES) ? g_deg[idx] : 0;
    s[t] = v;
    __syncthreads();
    for (int o = 1; o < SCAN_CHUNK; o <<= 1) {
        int x = (t >= o) ? s[t - o] : 0;
        __syncthreads();
        s[t] += x;
        __syncthreads();
    }
    int excl = s[t] - v + g_bsum[blockIdx.x];
    if (idx < NUM_NODES) {
        g_off[idx] = excl;
        g_pos[idx] = excl;
        if (idx == NUM_NODES - 1) g_off[NUM_NODES] = excl + v;
    }
}

// ---- 3. bucket edges by dst: one packed 8B store per edge ----
__global__ void bucket_kernel(const int* __restrict__ edge_src,
                              const int* __restrict__ edge_dst,
                              const float* __restrict__ edge_weight) {
    int e = blockIdx.x * blockDim.x + threadIdx.x;
    if (e >= NUM_EDGES) return;
    int d = __ldg(edge_dst + e);
    int p = atomicAdd(&g_pos[d], 1);
    int2 pk;
    pk.x = __ldg(edge_src + e);
    pk.y = __float_as_int(__ldg(edge_weight + e));
    g_edge[p] = pk;
}

__device__ __forceinline__ const float* x0_row_ptr(int s, const float* u, const float* it) {
    return (s < NUM_USERS) ? (u + (size_t)s * EMBED_DIM)
                           : (it + (size_t)(s - NUM_USERS) * EMBED_DIM);
}

// ---- 4. layer-1 gather, unroll 4 ----
__global__ void gather1_kernel(const float* __restrict__ u_embs,
                               const float* __restrict__ i_embs) {
    long long gid = (long long)blockIdx.x * blockDim.x + threadIdx.x;
    int n = (int)(gid >> 4);
    int c = (int)(gid & 15);
    if (n >= NUM_NODES) return;

    int b = __ldg(&g_off[n]);
    int e = __ldg(&g_off[n + 1]);
    float4 acc = make_float4(0.f, 0.f, 0.f, 0.f);

    int k = b;
    for (; k + 3 < e; k += 4) {
        int2 e0 = g_edge[k], e1 = g_edge[k + 1], e2 = g_edge[k + 2], e3 = g_edge[k + 3];
        float4 v0 = *(const float4*)(x0_row_ptr(e0.x, u_embs, i_embs) + c * 4);
        float4 v1 = *(const float4*)(x0_row_ptr(e1.x, u_embs, i_embs) + c * 4);
        float4 v2 = *(const float4*)(x0_row_ptr(e2.x, u_embs, i_embs) + c * 4);
        float4 v3 = *(const float4*)(x0_row_ptr(e3.x, u_embs, i_embs) + c * 4);
        float w0 = __int_as_float(e0.y), w1 = __int_as_float(e1.y);
        float w2 = __int_as_float(e2.y), w3 = __int_as_float(e3.y);
        acc.x += w0 * v0.x + w1 * v1.x + w2 * v2.x + w3 * v3.x;
        acc.y += w0 * v0.y + w1 * v1.y + w2 * v2.y + w3 * v3.y;
        acc.z += w0 * v0.z + w1 * v1.z + w2 * v2.z + w3 * v3.z;
        acc.w += w0 * v0.w + w1 * v1.w + w2 * v2.w + w3 * v3.w;
    }
    for (; k < e; k++) {
        int2 e0 = g_edge[k];
        float w0 = __int_as_float(e0.y);
        float4 v0 = *(const float4*)(x0_row_ptr(e0.x, u_embs, i_embs) + c * 4);
        acc.x += w0 * v0.x; acc.y += w0 * v0.y;
        acc.z += w0 * v0.z; acc.w += w0 * v0.w;
    }
    *(float4*)(g_x1 + (size_t)n * EMBED_DIM + c * 4) = acc;
}

// ---- 5. layer-2 gather fused with finalize ----
__global__ void gather2_fin_kernel(const float* __restrict__ u_embs,
                                   const float* __restrict__ i_embs,
                                   float* __restrict__ out) {
    long long gid = (long long)blockIdx.x * blockDim.x + threadIdx.x;
    int n = (int)(gid >> 4);
    int c = (int)(gid & 15);
    if (n >= NUM_NODES) return;

    int b = __ldg(&g_off[n]);
    int e = __ldg(&g_off[n + 1]);
    float4 acc = make_float4(0.f, 0.f, 0.f, 0.f);

    int k = b;
    for (; k + 3 < e; k += 4) {
        int2 e0 = g_edge[k], e1 = g_edge[k + 1], e2 = g_edge[k + 2], e3 = g_edge[k + 3];
        float4 v0 = *(const float4*)(g_x1 + (size_t)e0.x * EMBED_DIM + c * 4);
        float4 v1 = *(const float4*)(g_x1 + (size_t)e1.x * EMBED_DIM + c * 4);
        float4 v2 = *(const float4*)(g_x1 + (size_t)e2.x * EMBED_DIM + c * 4);
        float4 v3 = *(const float4*)(g_x1 + (size_t)e3.x * EMBED_DIM + c * 4);
        float w0 = __int_as_float(e0.y), w1 = __int_as_float(e1.y);
        float w2 = __int_as_float(e2.y), w3 = __int_as_float(e3.y);
        acc.x += w0 * v0.x + w1 * v1.x + w2 * v2.x + w3 * v3.x;
        acc.y += w0 * v0.y + w1 * v1.y + w2 * v2.y + w3 * v3.y;
        acc.z += w0 * v0.z + w1 * v1.z + w2 * v2.z + w3 * v3.z;
        acc.w += w0 * v0.w + w1 * v1.w + w2 * v2.w + w3 * v3.w;
    }
    for (; k < e; k++) {
        int2 e0 = g_edge[k];
        float w0 = __int_as_float(e0.y);
        float4 v0 = *(const float4*)(g_x1 + (size_t)e0.x * EMBED_DIM + c * 4);
        acc.x += w0 * v0.x; acc.y += w0 * v0.y;
        acc.z += w0 * v0.z; acc.w += w0 * v0.w;
    }

    const float* x0_row = x0_row_ptr(n, u_embs, i_embs);
    float4 a  = *(const float4*)(x0_row + c * 4);
    float4 b1 = *(const float4*)(g_x1 + (size_t)n * EMBED_DIM + c * 4);

    const float inv3 = 1.0f / 3.0f;
    float4 r;
    r.x = (a.x + b1.x + acc.x) * inv3;
    r.y = (a.y + b1.y + acc.y) * inv3;
    r.z = (a.z + b1.z + acc.z) * inv3;
    r.w = (a.w + b1.w + acc.w) * inv3;
    *(float4*)(out + (size_t)n * EMBED_DIM + c * 4) = r;
}

extern "C" void kernel_launch(void* const* d_in, const int* in_sizes, int n_in,
                              void* d_out, int out_size) {
    const float* u_embs      = (const float*)d_in[0];
    const float* i_embs      = (const float*)d_in[1];
    const int*   edge_src    = (const int*)d_in[2];
    const int*   edge_dst    = (const int*)d_in[3];
    const float* edge_weight = (const float*)d_in[4];
    float* out = (float*)d_out;

    void* deg_ptr = nullptr;
    cudaGetSymbolAddress(&deg_ptr, g_deg);
    cudaMemsetAsync(deg_ptr, 0, NUM_NODES * sizeof(int), 0);

    // histogram (4 edges per thread)
    {
        int nthr = (NUM_EDGES + 3) / 4;
        hist_kernel<<<(nthr + 255) / 256, 256>>>(edge_dst);
    }

    // prefix scan of degrees -> offsets + cursors
    block_sum_kernel<<<NUM_SCAN_BLOCKS, SCAN_CHUNK>>>();
    scan_bsum_kernel<<<1, 512>>>();
    offsets_kernel<<<NUM_SCAN_BLOCKS, SCAN_CHUNK>>>();

    // bucket edges by dst (packed 8B store)
    bucket_kernel<<<(NUM_EDGES + 255) / 256, 256>>>(edge_src, edge_dst, edge_weight);

    // layer 1 gather
    {
        long long total = (long long)NUM_NODES * 16;
        int threads = 256;
        int blocks = (int)((total + threads - 1) / threads);
        gather1_kernel<<<blocks, threads>>>(u_embs, i_embs);
    }

    // layer 2 gather + finalize
    {
        long long total = (long long)NUM_NODES * 16;
        int threads = 256;
        int blocks = (int)((total + threads - 1) / threads);
        gather2_fin_kernel<<<blocks, threads>>>(u_embs, i_embs, out);
    }
}

// round 5
// speedup vs baseline: 1.0599x; 1.0599x over previous
#include <cuda_runtime.h>
#include <cstdint>

#define NUM_USERS 200000
#define NUM_ITEMS 100000
#define NUM_NODES (NUM_USERS + NUM_ITEMS)
#define EMBED_DIM 64
#define NUM_EDGES 2000000

#define SCAN_CHUNK 1024
#define NUM_SCAN_BLOCKS ((NUM_NODES + SCAN_CHUNK - 1) / SCAN_CHUNK)  // 293

// ---- device-global scratch (no allocation allowed) ----
// g_deg has one extra slot: g_deg[NUM_NODES] is the chunk-base allocation counter.
__device__ int   g_deg[NUM_NODES + 1];
__device__ int   g_off[NUM_NODES];
__device__ int   g_pos[NUM_NODES];
__device__ int2  g_edge[NUM_EDGES];          // packed (src, weight-bits)
__device__ float g_x1[(size_t)NUM_NODES * EMBED_DIM];

// ---- 1. histogram of dst degrees (scalar, 1 edge/thread: known-good) ----
__global__ void hist_kernel(const int* __restrict__ edge_dst) {
    int e = blockIdx.x * blockDim.x + threadIdx.x;
    if (e >= NUM_EDGES) return;
    atomicAdd(&g_deg[__ldg(edge_dst + e)], 1);   // no return -> RED
}

// ---- 2. single-kernel scan: chunk-local exclusive scan + atomic chunk base ----
// Chunk bases are arrival-ordered (NOT monotone in node index). That is fine:
// buckets only need to be disjoint; gather computes end = off[n] + deg[n].
__global__ void scan_kernel() {
    __shared__ int s[SCAN_CHUNK];
    __shared__ int base_sh;
    int t = threadIdx.x;
    int idx = blockIdx.x * SCAN_CHUNK + t;
    int v = (idx < NUM_NODES) ? g_deg[idx] : 0;
    s[t] = v;
    __syncthreads();
    // inclusive scan (Hillis-Steele)
    for (int o = 1; o < SCAN_CHUNK; o <<= 1) {
        int x = (t >= o) ? s[t - o] : 0;
        __syncthreads();
        s[t] += x;
        __syncthreads();
    }
    if (t == SCAN_CHUNK - 1) {
        // allocate this chunk's contiguous range
        base_sh = atomicAdd(&g_deg[NUM_NODES], s[t]);
    }
    __syncthreads();
    if (idx < NUM_NODES) {
        int excl = s[t] - v + base_sh;
        g_off[idx] = excl;
        g_pos[idx] = excl;
    }
}

// ---- 3. bucket edges by dst: one packed 8B store per edge ----
__global__ void bucket_kernel(const int* __restrict__ edge_src,
                              const int* __restrict__ edge_dst,
                              const float* __restrict__ edge_weight) {
    int e = blockIdx.x * blockDim.x + threadIdx.x;
    if (e >= NUM_EDGES) return;
    int d = __ldg(edge_dst + e);
    int p = atomicAdd(&g_pos[d], 1);
    int2 pk;
    pk.x = __ldg(edge_src + e);
    pk.y = __float_as_int(__ldg(edge_weight + e));
    g_edge[p] = pk;
}

__device__ __forceinline__ const float* x0_row_ptr(int s, const float* u, const float* it) {
    return (s < NUM_USERS) ? (u + (size_t)s * EMBED_DIM)
                           : (it + (size_t)(s - NUM_USERS) * EMBED_DIM);
}

// ---- 4. layer-1 gather: unroll-2 main + single predicated tail (R2 structure) ----
__global__ void gather1_kernel(const float* __restrict__ u_embs,
                               const float* __restrict__ i_embs) {
    long long gid = (long long)blockIdx.x * blockDim.x + threadIdx.x;
    int n = (int)(gid >> 4);
    int c = (int)(gid & 15);
    if (n >= NUM_NODES) return;

    int b = __ldg(&g_off[n]);
    int e = b + __ldg(&g_deg[n]);
    float4 acc = make_float4(0.f, 0.f, 0.f, 0.f);

    int k = b;
    for (; k + 1 < e; k += 2) {
        int2 e0 = g_edge[k], e1 = g_edge[k + 1];
        float4 v0 = *(const float4*)(x0_row_ptr(e0.x, u_embs, i_embs) + c * 4);
        float4 v1 = *(const float4*)(x0_row_ptr(e1.x, u_embs, i_embs) + c * 4);
        float w0 = __int_as_float(e0.y), w1 = __int_as_float(e1.y);
        acc.x += w0 * v0.x + w1 * v1.x;
        acc.y += w0 * v0.y + w1 * v1.y;
        acc.z += w0 * v0.z + w1 * v1.z;
        acc.w += w0 * v0.w + w1 * v1.w;
    }
    if (k < e) {
        int2 e0 = g_edge[k];
        float w0 = __int_as_float(e0.y);
        float4 v0 = *(const float4*)(x0_row_ptr(e0.x, u_embs, i_embs) + c * 4);
        acc.x += w0 * v0.x; acc.y += w0 * v0.y;
        acc.z += w0 * v0.z; acc.w += w0 * v0.w;
    }
    *(float4*)(g_x1 + (size_t)n * EMBED_DIM + c * 4) = acc;
}

// ---- 5. layer-2 gather fused with finalize ----
__global__ void gather2_fin_kernel(const float* __restrict__ u_embs,
                                   const float* __restrict__ i_embs,
                                   float* __restrict__ out) {
    long long gid = (long long)blockIdx.x * blockDim.x + threadIdx.x;
    int n = (int)(gid >> 4);
    int c = (int)(gid & 15);
    if (n >= NUM_NODES) return;

    int b = __ldg(&g_off[n]);
    int e = b + __ldg(&g_deg[n]);
    float4 acc = make_float4(0.f, 0.f, 0.f, 0.f);

    int k = b;
    for (; k + 1 < e; k += 2) {
        int2 e0 = g_edge[k], e1 = g_edge[k + 1];
        float4 v0 = *(const float4*)(g_x1 + (size_t)e0.x * EMBED_DIM + c * 4);
        float4 v1 = *(const float4*)(g_x1 + (size_t)e1.x * EMBED_DIM + c * 4);
        float w0 = __int_as_float(e0.y), w1 = __int_as_float(e1.y);
        acc.x += w0 * v0.x + w1 * v1.x;
        acc.y += w0 * v0.y + w1 * v1.y;
        acc.z += w0 * v0.z + w1 * v1.z;
        acc.w += w0 * v0.w + w1 * v1.w;
    }
    if (k < e) {
        int2 e0 = g_edge[k];
        float w0 = __int_as_float(e0.y);
        float4 v0 = *(const float4*)(g_x1 + (size_t)e0.x * EMBED_DIM + c * 4);
        acc.x += w0 * v0.x; acc.y += w0 * v0.y;
        acc.z += w0 * v0.z; acc.w += w0 * v0.w;
    }

    const float* x0_row = x0_row_ptr(n, u_embs, i_embs);
    float4 a  = *(const float4*)(x0_row + c * 4);
    float4 b1 = *(const float4*)(g_x1 + (size_t)n * EMBED_DIM + c * 4);

    const float inv3 = 1.0f / 3.0f;
    float4 r;
    r.x = (a.x + b1.x + acc.x) * inv3;
    r.y = (a.y + b1.y + acc.y) * inv3;
    r.z = (a.z + b1.z + acc.z) * inv3;
    r.w = (a.w + b1.w + acc.w) * inv3;
    *(float4*)(out + (size_t)n * EMBED_DIM + c * 4) = r;
}

extern "C" void kernel_launch(void* const* d_in, const int* in_sizes, int n_in,
                              void* d_out, int out_size) {
    const float* u_embs      = (const float*)d_in[0];
    const float* i_embs      = (const float*)d_in[1];
    const int*   edge_src    = (const int*)d_in[2];
    const int*   edge_dst    = (const int*)d_in[3];
    const float* edge_weight = (const float*)d_in[4];
    float* out = (float*)d_out;

    void* deg_ptr = nullptr;
    cudaGetSymbolAddress(&deg_ptr, g_deg);
    // zero degrees + the chunk-base counter (last slot) in one memset
    cudaMemsetAsync(deg_ptr, 0, (NUM_NODES + 1) * sizeof(int), 0);

    // histogram
    hist_kernel<<<(NUM_EDGES + 255) / 256, 256>>>(edge_dst);

    // single-kernel scan -> offsets + cursors
    scan_kernel<<<NUM_SCAN_BLOCKS, SCAN_CHUNK>>>();

    // bucket edges by dst (packed 8B store)
    bucket_kernel<<<(NUM_EDGES + 255) / 256, 256>>>(edge_src, edge_dst, edge_weight);

    // layer 1 gather
    {
        long long total = (long long)NUM_NODES * 16;
        int threads = 256;
        int blocks = (int)((total + threads - 1) / threads);
        gather1_kernel<<<blocks, threads>>>(u_embs, i_embs);
    }

    // layer 2 gather + finalize
    {
        long long total = (long long)NUM_NODES * 16;
        int threads = 256;
        int blocks = (int)((total + threads - 1) / threads);
        gather2_fin_kernel<<<blocks, threads>>>(u_embs, i_embs, out);
    }
}

// round 7
// speedup vs baseline: 1.1309x; 1.0670x over previous
#include <cuda_runtime.h>
#include <cstdint>

#define NUM_USERS 200000
#define NUM_ITEMS 100000
#define NUM_NODES (NUM_USERS + NUM_ITEMS)
#define EMBED_DIM 64
#define NUM_EDGES 2000000

#define SCAN_CHUNK 1024
#define NUM_SCAN_BLOCKS ((NUM_NODES + SCAN_CHUNK - 1) / SCAN_CHUNK)  // 293

// ---- device-global scratch (no allocation allowed) ----
__device__ int   g_deg[NUM_NODES];
__device__ int   g_off[NUM_NODES + 1];
__device__ int   g_pos[NUM_NODES];
__device__ int   g_bsum[512];
__device__ int2  g_edge[NUM_EDGES];          // packed (src, weight-bits)
__device__ float g_x1[(size_t)NUM_NODES * EMBED_DIM];

// ---- 1. histogram of dst degrees ----
__global__ void hist_kernel(const int* __restrict__ edge_dst) {
    int e = blockIdx.x * blockDim.x + threadIdx.x;
    if (e >= NUM_EDGES) return;
    atomicAdd(&g_deg[__ldg(edge_dst + e)], 1);
}

// ---- 2a. per-chunk sums ----
__global__ void block_sum_kernel() {
    __shared__ int s[SCAN_CHUNK];
    int t = threadIdx.x;
    int idx = blockIdx.x * SCAN_CHUNK + t;
    s[t] = (idx < NUM_NODES) ? g_deg[idx] : 0;
    __syncthreads();
    for (int o = SCAN_CHUNK / 2; o > 0; o >>= 1) {
        if (t < o) s[t] += s[t + o];
        __syncthreads();
    }
    if (t == 0) g_bsum[blockIdx.x] = s[0];
}

// ---- 2b. scan chunk sums (single block) -> monotone chunk bases ----
__global__ void scan_bsum_kernel() {
    __shared__ int s[512];
    int t = threadIdx.x;
    int v = (t < NUM_SCAN_BLOCKS) ? g_bsum[t] : 0;
    s[t] = v;
    __syncthreads();
    for (int o = 1; o < 512; o <<= 1) {
        int x = (t >= o) ? s[t - o] : 0;
        __syncthreads();
        s[t] += x;
        __syncthreads();
    }
    if (t < NUM_SCAN_BLOCKS) g_bsum[t] = s[t] - v;  // exclusive
}

// ---- 2c. per-chunk exclusive scan + chunk base -> offsets & cursors ----
__global__ void offsets_kernel() {
    __shared__ int s[SCAN_CHUNK];
    int t = threadIdx.x;
    int idx = blockIdx.x * SCAN_CHUNK + t;
    int v = (idx < NUM_NODES) ? g_deg[idx] : 0;
    s[t] = v;
    __syncthreads();
    for (int o = 1; o < SCAN_CHUNK; o <<= 1) {
        int x = (t >= o) ? s[t - o] : 0;
        __syncthreads();
        s[t] += x;
        __syncthreads();
    }
    int excl = s[t] - v + g_bsum[blockIdx.x];
    if (idx < NUM_NODES) {
        g_off[idx] = excl;
        g_pos[idx] = excl;
        if (idx == NUM_NODES - 1) g_off[NUM_NODES] = excl + v;
    }
}

// ---- 3. bucket edges by dst: one packed 8B store per edge ----
__global__ void bucket_kernel(const int* __restrict__ edge_src,
                              const int* __restrict__ edge_dst,
                              const float* __restrict__ edge_weight) {
    int e = blockIdx.x * blockDim.x + threadIdx.x;
    if (e >= NUM_EDGES) return;
    int d = __ldg(edge_dst + e);
    int p = atomicAdd(&g_pos[d], 1);
    int2 pk;
    pk.x = __ldg(edge_src + e);
    pk.y = __float_as_int(__ldg(edge_weight + e));
    g_edge[p] = pk;
}

__device__ __forceinline__ const float* x0_row_ptr(int s, const float* u, const float* it) {
    return (s < NUM_USERS) ? (u + (size_t)s * EMBED_DIM)
                           : (it + (size_t)(s - NUM_USERS) * EMBED_DIM);
}

#define PIPE 4

// ---- 4. layer-1 gather: depth-4 double-buffered pipeline ----
__global__ void gather1_kernel(const float* __restrict__ u_embs,
                               const float* __restrict__ i_embs) {
    long long gid = (long long)blockIdx.x * blockDim.x + threadIdx.x;
    int n = (int)(gid >> 4);
    int c = (int)(gid & 15);
    if (n >= NUM_NODES) return;

    int b = __ldg(&g_off[n]);
    int e = __ldg(&g_off[n + 1]);
    int len = e - b;
    float4 acc = make_float4(0.f, 0.f, 0.f, 0.f);

    if (len > 0) {
        int2 E[PIPE];
        float4 V[PIPE];
        // prologue: batch 0 — all loads issue before any FMA
        #pragma unroll
        for (int i = 0; i < PIPE; i++) {
            int idx = b + ((i < len) ? i : (len - 1));   // clamp to valid edge
            E[i] = g_edge[idx];
            if (i >= len) E[i].y = 0;                    // zero weight for padding
        }
        #pragma unroll
        for (int i = 0; i < PIPE; i++)
            V[i] = *(const float4*)(x0_row_ptr(E[i].x, u_embs, i_embs) + c * 4);

        int k = b + PIPE;
        while (k < e) {
            int2 En[PIPE];
            #pragma unroll
            for (int i = 0; i < PIPE; i++) {
                int idx = (k + i < e) ? (k + i) : (e - 1);
                En[i] = g_edge[idx];
                if (k + i >= e) En[i].y = 0;
            }
            // FMA previous batch (its row loads have had a full batch to land)
            #pragma unroll
            for (int i = 0; i < PIPE; i++) {
                float w = __int_as_float(E[i].y);
                acc.x += w * V[i].x; acc.y += w * V[i].y;
                acc.z += w * V[i].z; acc.w += w * V[i].w;
            }
            #pragma unroll
            for (int i = 0; i < PIPE; i++) {
                V[i] = *(const float4*)(x0_row_ptr(En[i].x, u_embs, i_embs) + c * 4);
                E[i] = En[i];
            }
            k += PIPE;
        }
        // epilogue
        #pragma unroll
        for (int i = 0; i < PIPE; i++) {
            float w = __int_as_float(E[i].y);
            acc.x += w * V[i].x; acc.y += w * V[i].y;
            acc.z += w * V[i].z; acc.w += w * V[i].w;
        }
    }
    *(float4*)(g_x1 + (size_t)n * EMBED_DIM + c * 4) = acc;
}

// ---- 5. layer-2 gather fused with finalize ----
__global__ void gather2_fin_kernel(const float* __restrict__ u_embs,
                                   const float* __restrict__ i_embs,
                                   float* __restrict__ out) {
    long long gid = (long long)blockIdx.x * blockDim.x + threadIdx.x;
    int n = (int)(gid >> 4);
    int c = (int)(gid & 15);
    if (n >= NUM_NODES) return;

    int b = __ldg(&g_off[n]);
    int e = __ldg(&g_off[n + 1]);
    int len = e - b;
    float4 acc = make_float4(0.f, 0.f, 0.f, 0.f);

    if (len > 0) {
        int2 E[PIPE];
        float4 V[PIPE];
        #pragma unroll
        for (int i = 0; i < PIPE; i++) {
            int idx = b + ((i < len) ? i : (len - 1));
            E[i] = g_edge[idx];
            if (i >= len) E[i].y = 0;
        }
        #pragma unroll
        for (int i = 0; i < PIPE; i++)
            V[i] = *(const float4*)(g_x1 + (size_t)E[i].x * EMBED_DIM + c * 4);

        int k = b + PIPE;
        while (k < e) {
            int2 En[PIPE];
            #pragma unroll
            for (int i = 0; i < PIPE; i++) {
                int idx = (k + i < e) ? (k + i) : (e - 1);
                En[i] = g_edge[idx];
                if (k + i >= e) En[i].y = 0;
            }
            #pragma unroll
            for (int i = 0; i < PIPE; i++) {
                float w = __int_as_float(E[i].y);
                acc.x += w * V[i].x; acc.y += w * V[i].y;
                acc.z += w * V[i].z; acc.w += w * V[i].w;
            }
            #pragma unroll
            for (int i = 0; i < PIPE; i++) {
                V[i] = *(const float4*)(g_x1 + (size_t)En[i].x * EMBED_DIM + c * 4);
                E[i] = En[i];
            }
            k += PIPE;
        }
        #pragma unroll
        for (int i = 0; i < PIPE; i++) {
            float w = __int_as_float(E[i].y);
            acc.x += w * V[i].x; acc.y += w * V[i].y;
            acc.z += w * V[i].z; acc.w += w * V[i].w;
        }
    }

    const float* x0_row = x0_row_ptr(n, u_embs, i_embs);
    float4 a  = *(const float4*)(x0_row + c * 4);
    float4 b1 = *(const float4*)(g_x1 + (size_t)n * EMBED_DIM + c * 4);

    const float inv3 = 1.0f / 3.0f;
    float4 r;
    r.x = (a.x + b1.x + acc.x) * inv3;
    r.y = (a.y + b1.y + acc.y) * inv3;
    r.z = (a.z + b1.z + acc.z) * inv3;
    r.w = (a.w + b1.w + acc.w) * inv3;
    *(float4*)(out + (size_t)n * EMBED_DIM + c * 4) = r;
}

extern "C" void kernel_launch(void* const* d_in, const int* in_sizes, int n_in,
                              void* d_out, int out_size) {
    const float* u_embs      = (const float*)d_in[0];
    const float* i_embs      = (const float*)d_in[1];
    const int*   edge_src    = (const int*)d_in[2];
    const int*   edge_dst    = (const int*)d_in[3];
    const float* edge_weight = (const float*)d_in[4];
    float* out = (float*)d_out;

    void* deg_ptr = nullptr;
    cudaGetSymbolAddress(&deg_ptr, g_deg);
    cudaMemsetAsync(deg_ptr, 0, NUM_NODES * sizeof(int), 0);

    // histogram
    hist_kernel<<<(NUM_EDGES + 255) / 256, 256>>>(edge_dst);

    // monotone prefix scan of degrees -> offsets + cursors
    block_sum_kernel<<<NUM_SCAN_BLOCKS, SCAN_CHUNK>>>();
    scan_bsum_kernel<<<1, 512>>>();
    offsets_kernel<<<NUM_SCAN_BLOCKS, SCAN_CHUNK>>>();

    // bucket edges by dst (packed 8B store)
    bucket_kernel<<<(NUM_EDGES + 255) / 256, 256>>>(edge_src, edge_dst, edge_weight);

    // layer 1 gather
    {
        long long total = (long long)NUM_NODES * 16;
        int threads = 256;
        int blocks = (int)((total + threads - 1) / threads);
        gather1_kernel<<<blocks, threads>>>(u_embs, i_embs);
    }

    // layer 2 gather + finalize
    {
        long long total = (long long)NUM_NODES * 16;
        int threads = 256;
        int blocks = (int)((total + threads - 1) / threads);
        gather2_fin_kernel<<<blocks, threads>>>(u_embs, i_embs, out);
    }
}

// round 8
// speedup vs baseline: 1.1768x; 1.0406x over previous
#include <cuda_runtime.h>
#include <cuda_fp16.h>
#include <cstdint>

#define NUM_USERS 200000
#define NUM_ITEMS 100000
#define NUM_NODES (NUM_USERS + NUM_ITEMS)
#define EMBED_DIM 64
#define NUM_EDGES 2000000

#define SCAN_CHUNK 1024
#define NUM_SCAN_BLOCKS ((NUM_NODES + SCAN_CHUNK - 1) / SCAN_CHUNK)  // 293

// ---- device-global scratch (no allocation allowed) ----
__device__ int   g_deg[NUM_NODES];
__device__ int   g_off[NUM_NODES + 1];
__device__ int   g_pos[NUM_NODES];
__device__ int   g_bsum[512];
__device__ int2  g_edge[NUM_EDGES];                 // packed (src, weight-bits)
__device__ uint2 g_x1h[(size_t)NUM_NODES * 16];     // x1 in fp16: 4 halves per uint2 chunk

// ---- 1. histogram of dst degrees ----
__global__ void hist_kernel(const int* __restrict__ edge_dst) {
    int e = blockIdx.x * blockDim.x + threadIdx.x;
    if (e >= NUM_EDGES) return;
    atomicAdd(&g_deg[__ldg(edge_dst + e)], 1);
}

// ---- 2a. per-chunk sums ----
__global__ void block_sum_kernel() {
    __shared__ int s[SCAN_CHUNK];
    int t = threadIdx.x;
    int idx = blockIdx.x * SCAN_CHUNK + t;
    s[t] = (idx < NUM_NODES) ? g_deg[idx] : 0;
    __syncthreads();
    for (int o = SCAN_CHUNK / 2; o > 0; o >>= 1) {
        if (t < o) s[t] += s[t + o];
        __syncthreads();
    }
    if (t == 0) g_bsum[blockIdx.x] = s[0];
}

// ---- 2b. scan chunk sums (single block) -> monotone chunk bases ----
__global__ void scan_bsum_kernel() {
    __shared__ int s[512];
    int t = threadIdx.x;
    int v = (t < NUM_SCAN_BLOCKS) ? g_bsum[t] : 0;
    s[t] = v;
    __syncthreads();
    for (int o = 1; o < 512; o <<= 1) {
        int x = (t >= o) ? s[t - o] : 0;
        __syncthreads();
        s[t] += x;
        __syncthreads();
    }
    if (t < NUM_SCAN_BLOCKS) g_bsum[t] = s[t] - v;  // exclusive
}

// ---- 2c. per-chunk exclusive scan + chunk base -> offsets & cursors ----
__global__ void offsets_kernel() {
    __shared__ int s[SCAN_CHUNK];
    int t = threadIdx.x;
    int idx = blockIdx.x * SCAN_CHUNK + t;
    int v = (idx < NUM_NODES) ? g_deg[idx] : 0;
    s[t] = v;
    __syncthreads();
    for (int o = 1; o < SCAN_CHUNK; o <<= 1) {
        int x = (t >= o) ? s[t - o] : 0;
        __syncthreads();
        s[t] += x;
        __syncthreads();
    }
    int excl = s[t] - v + g_bsum[blockIdx.x];
    if (idx < NUM_NODES) {
        g_off[idx] = excl;
        g_pos[idx] = excl;
        if (idx == NUM_NODES - 1) g_off[NUM_NODES] = excl + v;
    }
}

// ---- 3. bucket edges by dst: one packed 8B store per edge ----
__global__ void bucket_kernel(const int* __restrict__ edge_src,
                              const int* __restrict__ edge_dst,
                              const float* __restrict__ edge_weight) {
    int e = blockIdx.x * blockDim.x + threadIdx.x;
    if (e >= NUM_EDGES) return;
    int d = __ldg(edge_dst + e);
    int p = atomicAdd(&g_pos[d], 1);
    int2 pk;
    pk.x = __ldg(edge_src + e);
    pk.y = __float_as_int(__ldg(edge_weight + e));
    g_edge[p] = pk;
}

__device__ __forceinline__ const float* x0_row_ptr(int s, const float* u, const float* it) {
    return (s < NUM_USERS) ? (u + (size_t)s * EMBED_DIM)
                           : (it + (size_t)(s - NUM_USERS) * EMBED_DIM);
}

__device__ __forceinline__ uint2 pack_h4(float4 a) {
    __half2 h0 = __floats2half2_rn(a.x, a.y);
    __half2 h1 = __floats2half2_rn(a.z, a.w);
    uint2 pk;
    pk.x = *(const unsigned int*)&h0;
    pk.y = *(const unsigned int*)&h1;
    return pk;
}

__device__ __forceinline__ float4 unpack_h4(uint2 pk) {
    __half2 h0 = *(const __half2*)&pk.x;
    __half2 h1 = *(const __half2*)&pk.y;
    float2 f0 = __half22float2(h0);
    float2 f1 = __half22float2(h1);
    return make_float4(f0.x, f0.y, f1.x, f1.y);
}

// ---- 4. layer-1 gather (R2 unroll-2 shape), fp16 output ----
__global__ void gather1_kernel(const float* __restrict__ u_embs,
                               const float* __restrict__ i_embs) {
    long long gid = (long long)blockIdx.x * blockDim.x + threadIdx.x;
    int n = (int)(gid >> 4);
    int c = (int)(gid & 15);
    if (n >= NUM_NODES) return;

    int b = __ldg(&g_off[n]);
    int e = __ldg(&g_off[n + 1]);
    float4 acc = make_float4(0.f, 0.f, 0.f, 0.f);

    int k = b;
    for (; k + 1 < e; k += 2) {
        int2 e0 = g_edge[k], e1 = g_edge[k + 1];
        float4 v0 = *(const float4*)(x0_row_ptr(e0.x, u_embs, i_embs) + c * 4);
        float4 v1 = *(const float4*)(x0_row_ptr(e1.x, u_embs, i_embs) + c * 4);
        float w0 = __int_as_float(e0.y), w1 = __int_as_float(e1.y);
        acc.x += w0 * v0.x + w1 * v1.x;
        acc.y += w0 * v0.y + w1 * v1.y;
        acc.z += w0 * v0.z + w1 * v1.z;
        acc.w += w0 * v0.w + w1 * v1.w;
    }
    if (k < e) {
        int2 e0 = g_edge[k];
        float w0 = __int_as_float(e0.y);
        float4 v0 = *(const float4*)(x0_row_ptr(e0.x, u_embs, i_embs) + c * 4);
        acc.x += w0 * v0.x; acc.y += w0 * v0.y;
        acc.z += w0 * v0.z; acc.w += w0 * v0.w;
    }
    g_x1h[(size_t)n * 16 + c] = pack_h4(acc);
}

// ---- 5. layer-2 gather (fp16 rows) fused with finalize (fp32 out) ----
__global__ void gather2_fin_kernel(const float* __restrict__ u_embs,
                                   const float* __restrict__ i_embs,
                                   float* __restrict__ out) {
    long long gid = (long long)blockIdx.x * blockDim.x + threadIdx.x;
    int n = (int)(gid >> 4);
    int c = (int)(gid & 15);
    if (n >= NUM_NODES) return;

    int b = __ldg(&g_off[n]);
    int e = __ldg(&g_off[n + 1]);
    float4 acc = make_float4(0.f, 0.f, 0.f, 0.f);

    int k = b;
    for (; k + 1 < e; k += 2) {
        int2 e0 = g_edge[k], e1 = g_edge[k + 1];
        float4 v0 = unpack_h4(g_x1h[(size_t)e0.x * 16 + c]);
        float4 v1 = unpack_h4(g_x1h[(size_t)e1.x * 16 + c]);
        float w0 = __int_as_float(e0.y), w1 = __int_as_float(e1.y);
        acc.x += w0 * v0.x + w1 * v1.x;
        acc.y += w0 * v0.y + w1 * v1.y;
        acc.z += w0 * v0.z + w1 * v1.z;
        acc.w += w0 * v0.w + w1 * v1.w;
    }
    if (k < e) {
        int2 e0 = g_edge[k];
        float w0 = __int_as_float(e0.y);
        float4 v0 = unpack_h4(g_x1h[(size_t)e0.x * 16 + c]);
        acc.x += w0 * v0.x; acc.y += w0 * v0.y;
        acc.z += w0 * v0.z; acc.w += w0 * v0.w;
    }

    const float* x0_row = x0_row_ptr(n, u_embs, i_embs);
    float4 a  = *(const float4*)(x0_row + c * 4);
    float4 b1 = unpack_h4(g_x1h[(size_t)n * 16 + c]);

    const float inv3 = 1.0f / 3.0f;
    float4 r;
    r.x = (a.x + b1.x + acc.x) * inv3;
    r.y = (a.y + b1.y + acc.y) * inv3;
    r.z = (a.z + b1.z + acc.z) * inv3;
    r.w = (a.w + b1.w + acc.w) * inv3;
    *(float4*)(out + (size_t)n * EMBED_DIM + c * 4) = r;
}

extern "C" void kernel_launch(void* const* d_in, const int* in_sizes, int n_in,
                              void* d_out, int out_size) {
    const float* u_embs      = (const float*)d_in[0];
    const float* i_embs      = (const float*)d_in[1];
    const int*   edge_src    = (const int*)d_in[2];
    const int*   edge_dst    = (const int*)d_in[3];
    const float* edge_weight = (const float*)d_in[4];
    float* out = (float*)d_out;

    void* deg_ptr = nullptr;
    cudaGetSymbolAddress(&deg_ptr, g_deg);
    cudaMemsetAsync(deg_ptr, 0, NUM_NODES * sizeof(int), 0);

    // histogram
    hist_kernel<<<(NUM_EDGES + 255) / 256, 256>>>(edge_dst);

    // monotone prefix scan of degrees -> offsets + cursors
    block_sum_kernel<<<NUM_SCAN_BLOCKS, SCAN_CHUNK>>>();
    scan_bsum_kernel<<<1, 512>>>();
    offsets_kernel<<<NUM_SCAN_BLOCKS, SCAN_CHUNK>>>();

    // bucket edges by dst (packed 8B store)
    bucket_kernel<<<(NUM_EDGES + 255) / 256, 256>>>(edge_src, edge_dst, edge_weight);

    // layer 1 gather (fp16 x1)
    {
        long long total = (long long)NUM_NODES * 16;
        int threads = 256;
        int blocks = (int)((total + threads - 1) / threads);
        gather1_kernel<<<blocks, threads>>>(u_embs, i_embs);
    }

    // layer 2 gather + finalize
    {
        long long total = (long long)NUM_NODES * 16;
        int threads = 256;
        int blocks = (int)((total + threads - 1) / threads);
        gather2_fin_kernel<<<blocks, threads>>>(u_embs, i_embs, out);
    }
}

// round 9
// speedup vs baseline: 1.5261x; 1.2969x over previous
#include <cuda_runtime.h>
#include <cuda_fp16.h>
#include <cstdint>

#define NUM_USERS 200000
#define NUM_ITEMS 100000
#define NUM_NODES (NUM_USERS + NUM_ITEMS)
#define EMBED_DIM 64
#define NUM_EDGES 2000000

#define SCAN_CHUNK 1024
#define NUM_SCAN_BLOCKS ((NUM_NODES + SCAN_CHUNK - 1) / SCAN_CHUNK)  // 293

// ---- device-global scratch (no allocation allowed) ----
__device__ int   g_deg[NUM_NODES];
__device__ int   g_off[NUM_NODES + 1];
__device__ int   g_pos[NUM_NODES];
__device__ int   g_bsum[512];
__device__ int2  g_edge[NUM_EDGES];                 // packed (src, weight-bits)
__device__ uint4 g_x0h[(size_t)NUM_NODES * 8];      // x0 in fp16: 8 halves per uint4
__device__ uint4 g_x1h[(size_t)NUM_NODES * 8];      // x1 in fp16

// ---- 1. histogram of dst degrees ----
__global__ void hist_kernel(const int* __restrict__ edge_dst) {
    int e = blockIdx.x * blockDim.x + threadIdx.x;
    if (e >= NUM_EDGES) return;
    atomicAdd(&g_deg[__ldg(edge_dst + e)], 1);
}

// ---- 2a. per-chunk sums ----
__global__ void block_sum_kernel() {
    __shared__ int s[SCAN_CHUNK];
    int t = threadIdx.x;
    int idx = blockIdx.x * SCAN_CHUNK + t;
    s[t] = (idx < NUM_NODES) ? g_deg[idx] : 0;
    __syncthreads();
    for (int o = SCAN_CHUNK / 2; o > 0; o >>= 1) {
        if (t < o) s[t] += s[t + o];
        __syncthreads();
    }
    if (t == 0) g_bsum[blockIdx.x] = s[0];
}

// ---- 2b. scan chunk sums (single block) -> monotone chunk bases ----
__global__ void scan_bsum_kernel() {
    __shared__ int s[512];
    int t = threadIdx.x;
    int v = (t < NUM_SCAN_BLOCKS) ? g_bsum[t] : 0;
    s[t] = v;
    __syncthreads();
    for (int o = 1; o < 512; o <<= 1) {
        int x = (t >= o) ? s[t - o] : 0;
        __syncthreads();
        s[t] += x;
        __syncthreads();
    }
    if (t < NUM_SCAN_BLOCKS) g_bsum[t] = s[t] - v;  // exclusive
}

// ---- 2c. per-chunk exclusive scan + chunk base -> offsets & cursors ----
__global__ void offsets_kernel() {
    __shared__ int s[SCAN_CHUNK];
    int t = threadIdx.x;
    int idx = blockIdx.x * SCAN_CHUNK + t;
    int v = (idx < NUM_NODES) ? g_deg[idx] : 0;
    s[t] = v;
    __syncthreads();
    for (int o = 1; o < SCAN_CHUNK; o <<= 1) {
        int x = (t >= o) ? s[t - o] : 0;
        __syncthreads();
        s[t] += x;
        __syncthreads();
    }
    int excl = s[t] - v + g_bsum[blockIdx.x];
    if (idx < NUM_NODES) {
        g_off[idx] = excl;
        g_pos[idx] = excl;
        if (idx == NUM_NODES - 1) g_off[NUM_NODES] = excl + v;
    }
}

// ---- 3. bucket edges by dst: one packed 8B store per edge ----
__global__ void bucket_kernel(const int* __restrict__ edge_src,
                              const int* __restrict__ edge_dst,
                              const float* __restrict__ edge_weight) {
    int e = blockIdx.x * blockDim.x + threadIdx.x;
    if (e >= NUM_EDGES) return;
    int d = __ldg(edge_dst + e);
    int p = atomicAdd(&g_pos[d], 1);
    int2 pk;
    pk.x = __ldg(edge_src + e);
    pk.y = __float_as_int(__ldg(edge_weight + e));
    g_edge[p] = pk;
}

__device__ __forceinline__ const float* x0_row_ptr(int s, const float* u, const float* it) {
    return (s < NUM_USERS) ? (u + (size_t)s * EMBED_DIM)
                           : (it + (size_t)(s - NUM_USERS) * EMBED_DIM);
}

struct F8 { float v[8]; };

__device__ __forceinline__ F8 unpack_h8(uint4 pk) {
    F8 r;
    float2 f0 = __half22float2(*(const __half2*)&pk.x);
    float2 f1 = __half22float2(*(const __half2*)&pk.y);
    float2 f2 = __half22float2(*(const __half2*)&pk.z);
    float2 f3 = __half22float2(*(const __half2*)&pk.w);
    r.v[0] = f0.x; r.v[1] = f0.y; r.v[2] = f1.x; r.v[3] = f1.y;
    r.v[4] = f2.x; r.v[5] = f2.y; r.v[6] = f3.x; r.v[7] = f3.y;
    return r;
}

__device__ __forceinline__ uint4 pack_h8(const F8& a) {
    __half2 h0 = __floats2half2_rn(a.v[0], a.v[1]);
    __half2 h1 = __floats2half2_rn(a.v[2], a.v[3]);
    __half2 h2 = __floats2half2_rn(a.v[4], a.v[5]);
    __half2 h3 = __floats2half2_rn(a.v[6], a.v[7]);
    uint4 pk;
    pk.x = *(const unsigned int*)&h0;
    pk.y = *(const unsigned int*)&h1;
    pk.z = *(const unsigned int*)&h2;
    pk.w = *(const unsigned int*)&h3;
    return pk;
}

// ---- 0. convert x0 -> fp16 (coalesced streaming) ----
// thread owns 8 consecutive floats (32B read, 16B write)
__global__ void convert_kernel(const float* __restrict__ u_embs,
                               const float* __restrict__ i_embs) {
    long long gid = (long long)blockIdx.x * blockDim.x + threadIdx.x;
    long long total = (long long)NUM_NODES * 8;
    if (gid >= total) return;
    int n = (int)(gid >> 3);
    int c = (int)(gid & 7);
    const float* row = x0_row_ptr(n, u_embs, i_embs);
    float4 a = *(const float4*)(row + c * 8);
    float4 b = *(const float4*)(row + c * 8 + 4);
    F8 f;
    f.v[0] = a.x; f.v[1] = a.y; f.v[2] = a.z; f.v[3] = a.w;
    f.v[4] = b.x; f.v[5] = b.y; f.v[6] = b.z; f.v[7] = b.w;
    g_x0h[gid] = pack_h8(f);
}

// ---- 4. layer-1 gather: 8 lanes/node, fp16 rows in and out ----
__global__ void gather1_kernel() {
    long long gid = (long long)blockIdx.x * blockDim.x + threadIdx.x;
    int n = (int)(gid >> 3);
    int c = (int)(gid & 7);
    if (n >= NUM_NODES) return;

    int b = __ldg(&g_off[n]);
    int e = __ldg(&g_off[n + 1]);
    F8 acc;
    #pragma unroll
    for (int i = 0; i < 8; i++) acc.v[i] = 0.f;

    int k = b;
    for (; k + 1 < e; k += 2) {
        int2 e0 = g_edge[k], e1 = g_edge[k + 1];
        uint4 p0 = g_x0h[(size_t)e0.x * 8 + c];
        uint4 p1 = g_x0h[(size_t)e1.x * 8 + c];
        float w0 = __int_as_float(e0.y), w1 = __int_as_float(e1.y);
        F8 v0 = unpack_h8(p0), v1 = unpack_h8(p1);
        #pragma unroll
        for (int i = 0; i < 8; i++)
            acc.v[i] += w0 * v0.v[i] + w1 * v1.v[i];
    }
    if (k < e) {
        int2 e0 = g_edge[k];
        float w0 = __int_as_float(e0.y);
        F8 v0 = unpack_h8(g_x0h[(size_t)e0.x * 8 + c]);
        #pragma unroll
        for (int i = 0; i < 8; i++)
            acc.v[i] += w0 * v0.v[i];
    }
    g_x1h[(size_t)n * 8 + c] = pack_h8(acc);
}

// ---- 5. layer-2 gather (fp16 rows) fused with finalize (fp32 x0 + out) ----
__global__ void gather2_fin_kernel(const float* __restrict__ u_embs,
                                   const float* __restrict__ i_embs,
                                   float* __restrict__ out) {
    long long gid = (long long)blockIdx.x * blockDim.x + threadIdx.x;
    int n = (int)(gid >> 3);
    int c = (int)(gid & 7);
    if (n >= NUM_NODES) return;

    int b = __ldg(&g_off[n]);
    int e = __ldg(&g_off[n + 1]);
    F8 acc;
    #pragma unroll
    for (int i = 0; i < 8; i++) acc.v[i] = 0.f;

    int k = b;
    for (; k + 1 < e; k += 2) {
        int2 e0 = g_edge[k], e1 = g_edge[k + 1];
        uint4 p0 = g_x1h[(size_t)e0.x * 8 + c];
        uint4 p1 = g_x1h[(size_t)e1.x * 8 + c];
        float w0 = __int_as_float(e0.y), w1 = __int_as_float(e1.y);
        F8 v0 = unpack_h8(p0), v1 = unpack_h8(p1);
        #pragma unroll
        for (int i = 0; i < 8; i++)
            acc.v[i] += w0 * v0.v[i] + w1 * v1.v[i];
    }
    if (k < e) {
        int2 e0 = g_edge[k];
        float w0 = __int_as_float(e0.y);
        F8 v0 = unpack_h8(g_x1h[(size_t)e0.x * 8 + c]);
        #pragma unroll
        for (int i = 0; i < 8; i++)
            acc.v[i] += w0 * v0.v[i];
    }

    // finalize: fp32 x0 row (accuracy) + fp16 x1 row + acc
    const float* x0_row = x0_row_ptr(n, u_embs, i_embs);
    float4 a0 = *(const float4*)(x0_row + c * 8);
    float4 a1 = *(const float4*)(x0_row + c * 8 + 4);
    F8 b1 = unpack_h8(g_x1h[(size_t)n * 8 + c]);

    const float inv3 = 1.0f / 3.0f;
    float4 r0, r1;
    r0.x = (a0.x + b1.v[0] + acc.v[0]) * inv3;
    r0.y = (a0.y + b1.v[1] + acc.v[1]) * inv3;
    r0.z = (a0.z + b1.v[2] + acc.v[2]) * inv3;
    r0.w = (a0.w + b1.v[3] + acc.v[3]) * inv3;
    r1.x = (a1.x + b1.v[4] + acc.v[4]) * inv3;
    r1.y = (a1.y + b1.v[5] + acc.v[5]) * inv3;
    r1.z = (a1.z + b1.v[6] + acc.v[6]) * inv3;
    r1.w = (a1.w + b1.v[7] + acc.v[7]) * inv3;
    *(float4*)(out + (size_t)n * EMBED_DIM + c * 8)     = r0;
    *(float4*)(out + (size_t)n * EMBED_DIM + c * 8 + 4) = r1;
}

extern "C" void kernel_launch(void* const* d_in, const int* in_sizes, int n_in,
                              void* d_out, int out_size) {
    const float* u_embs      = (const float*)d_in[0];
    const float* i_embs      = (const float*)d_in[1];
    const int*   edge_src    = (const int*)d_in[2];
    const int*   edge_dst    = (const int*)d_in[3];
    const float* edge_weight = (const float*)d_in[4];
    float* out = (float*)d_out;

    void* deg_ptr = nullptr;
    cudaGetSymbolAddress(&deg_ptr, g_deg);
    cudaMemsetAsync(deg_ptr, 0, NUM_NODES * sizeof(int), 0);

    // convert x0 -> fp16 (independent of hist/scan; scheduled first)
    {
        long long total = (long long)NUM_NODES * 8;
        int threads = 256;
        int blocks = (int)((total + threads - 1) / threads);
        convert_kernel<<<blocks, threads>>>(u_embs, i_embs);
    }

    // histogram
    hist_kernel<<<(NUM_EDGES + 255) / 256, 256>>>(edge_dst);

    // monotone prefix scan of degrees -> offsets + cursors
    block_sum_kernel<<<NUM_SCAN_BLOCKS, SCAN_CHUNK>>>();
    scan_bsum_kernel<<<1, 512>>>();
    offsets_kernel<<<NUM_SCAN_BLOCKS, SCAN_CHUNK>>>();

    // bucket edges by dst (packed 8B store)
    bucket_kernel<<<(NUM_EDGES + 255) / 256, 256>>>(edge_src, edge_dst, edge_weight);

    // layer 1 gather (fp16 in/out, 8 lanes per node)
    {
        long long total = (long long)NUM_NODES * 8;
        int threads = 256;
        int blocks = (int)((total + threads - 1) / threads);
        gather1_kernel<<<blocks, threads>>>();
    }

    // layer 2 gather + finalize
    {
        long long total = (long long)NUM_NODES * 8;
        int threads = 256;
        int blocks = (int)((total + threads - 1) / threads);
        gather2_fin_kernel<<<blocks, threads>>>(u_embs, i_embs, out);
    }
}